// round 15
// baseline (speedup 1.0000x reference)
#include <cuda_runtime.h>

typedef unsigned long long u64;
typedef unsigned int u32;

#define SEQ   2048
#define DM    1024
#define NH    8
#define HD    128
#define NB    2
#define NROWS (NB*NH*SEQ)
#define TOPK  32

__device__ int   g_topk[NROWS*TOPK];
__device__ float g_zpart[4][NROWS];

__device__ __forceinline__ u32 fkey(float f){
    u32 b = __float_as_uint(f);
    return (b & 0x80000000u) ? ~b : (b | 0x80000000u);
}

// ===================== tf32 helpers =====================
__device__ __forceinline__ u32 cvt_tf32(float x){
    u32 r; asm("cvt.rna.tf32.f32 %0, %1;" : "=r"(r) : "f"(x)); return r;
}
__device__ __forceinline__ void mma_tf32(float* c, const u32* a, const u32* b){
    asm volatile("mma.sync.aligned.m16n8k8.row.col.f32.tf32.tf32.f32 "
        "{%0,%1,%2,%3}, {%4,%5,%6,%7}, {%8,%9}, {%0,%1,%2,%3};"
        : "+f"(c[0]), "+f"(c[1]), "+f"(c[2]), "+f"(c[3])
        : "r"(a[0]), "r"(a[1]), "r"(a[2]), "r"(a[3]), "r"(b[0]), "r"(b[1]));
}

// ---------------------------------------------------------------------------
// Kernel 2 (launched FIRST for ncu): partial Z per (hb, 128-q tile, 512-key
// slice) via tf32 mma.sync 3-pass split (hi*hi + hi*lo + lo*hi).
// 512 threads / 16 warps. Warp = (pos, dh): pos = wid&7 -> (wq=pos>>1: 32 q,
// wk=pos&1: 32 keys of the 64-key subtile); dh = wid>>3 -> k8-slices
// [8dh, 8dh+8). 32q x 32k warp tile keeps LDS at 171 B/MMA (< crossbar),
// d-split gives 4 warps/SMSP for latency hiding. Partial scores are summed
// across the (dh=0, dh=1) pair through a 16 KB smem exchange (2 rounds),
// then exp'd (s = s0+s1 must be summed BEFORE exp).
// Q hi/lo staged once (pad-132 rows, conflict-free fragment loads);
// K streamed in 64-key subtiles with register prefetch.
// No max-tracking (|score| <~ 75, exp can't overflow fp32).
// ---------------------------------------------------------------------------
#define APAD 132
#define AL_OFF (128*APAD)                   /* 16896 */
#define KH_OFF (2*128*APAD)                 /* 33792 */
#define KL_OFF (2*128*APAD + 64*APAD)       /* 42240 */
#define XB_OFF (2*128*APAD + 2*64*APAD)     /* 50688 */
#define ZR_OFF (XB_OFF + 4096)              /* 54784 */
#define SMEMZ_BYTES ((ZR_OFF + 256)*4)      /* 220160 B */

__global__ __launch_bounds__(512,1) void mz_kernel(const float* __restrict__ q,
                                                   const float* __restrict__ k){
    extern __shared__ u32 sm[];
    u32* Ah = sm;
    u32* Al = sm + AL_OFF;
    u32* Kh = sm + KH_OFF;
    u32* Kl = sm + KL_OFF;
    float* xbuf = (float*)(sm + XB_OFF);    // 4 x 1024 floats (2 rounds)
    float* zr   = (float*)(sm + ZR_OFF);    // [2 wk][128 q]

    const int t  = threadIdx.x;
    const int hb = blockIdx.x >> 6, qt = (blockIdx.x >> 2) & 15, kq = blockIdx.x & 3;
    const int b  = hb >> 3, h = hb & 7;
    const float* Qg = q + ((size_t)(b*SEQ + qt*128))*DM + h*HD;
    const float* Kg = k + ((size_t)(b*SEQ + kq*512))*DM + h*HD;

    const int lane = t & 31, wid = t >> 5;
    const int g = lane >> 2, tg = lane & 3;
    const int pos = wid & 7, dh = wid >> 3;
    const int wq = pos >> 1, wk = pos & 1;

    // ---- Q tile -> smem (tf32 hi/lo), once ----
#pragma unroll
    for (int mm = 0; mm < 8; ++mm){
        int f4 = mm*512 + t;
        int row = f4 >> 5, c4 = (f4 & 31)*4;
        float4 v = *(const float4*)(Qg + (size_t)row*DM + c4);
        float xs[4] = {v.x, v.y, v.z, v.w};
        u32 hb4[4], lb4[4];
#pragma unroll
        for (int j = 0; j < 4; ++j){
            u32 hi = cvt_tf32(xs[j]);
            hb4[j] = hi;
            lb4[j] = cvt_tf32(xs[j] - __uint_as_float(hi));
        }
        *(uint4*)&Ah[row*APAD + c4] = make_uint4(hb4[0],hb4[1],hb4[2],hb4[3]);
        *(uint4*)&Al[row*APAD + c4] = make_uint4(lb4[0],lb4[1],lb4[2],lb4[3]);
    }

    float z[4] = {0.f, 0.f, 0.f, 0.f};
    float4 pf[4];

    // prefetch K subtile 0 (64 keys x 128 dims)
#pragma unroll
    for (int i = 0; i < 4; ++i){
        int f4 = i*512 + t;
        int row = f4 >> 5, c4 = (f4 & 31)*4;
        pf[i] = *(const float4*)(Kg + (size_t)row*DM + c4);
    }

    for (int s = 0; s < 8; ++s){
        // stage prefetched subtile (cvt to hi/lo)
#pragma unroll
        for (int i = 0; i < 4; ++i){
            int f4 = i*512 + t;
            int row = f4 >> 5, c4 = (f4 & 31)*4;
            float xs[4] = {pf[i].x, pf[i].y, pf[i].z, pf[i].w};
            u32 hb4[4], lb4[4];
#pragma unroll
            for (int j = 0; j < 4; ++j){
                u32 hi = cvt_tf32(xs[j]);
                hb4[j] = hi;
                lb4[j] = cvt_tf32(xs[j] - __uint_as_float(hi));
            }
            *(uint4*)&Kh[row*APAD + c4] = make_uint4(hb4[0],hb4[1],hb4[2],hb4[3]);
            *(uint4*)&Kl[row*APAD + c4] = make_uint4(lb4[0],lb4[1],lb4[2],lb4[3]);
        }
        __syncthreads();

        // prefetch next subtile during compute
        if (s < 7){
#pragma unroll
            for (int i = 0; i < 4; ++i){
                int f4 = i*512 + t;
                int row = f4 >> 5, c4 = (f4 & 31)*4;
                pf[i] = *(const float4*)(Kg + (size_t)((s+1)*64 + row)*DM + c4);
            }
        }

        float c[2][4][4];
#pragma unroll
        for (int m = 0; m < 2; ++m)
#pragma unroll
            for (int n = 0; n < 4; ++n)
#pragma unroll
                for (int j = 0; j < 4; ++j) c[m][n][j] = 0.f;

        // this warp's 8 k8-slices (d-split)
#pragma unroll 2
        for (int sl = 0; sl < 8; ++sl){
            int d0 = (dh*8 + sl)*8;
            u32 ah[2][4], al[2][4], bh[4][2], bl[4][2];
#pragma unroll
            for (int m = 0; m < 2; ++m){
                int r0 = (32*wq + 16*m + g)*APAD + d0 + tg;
                ah[m][0] = Ah[r0];     ah[m][1] = Ah[r0 + 8*APAD];
                ah[m][2] = Ah[r0 + 4]; ah[m][3] = Ah[r0 + 8*APAD + 4];
                al[m][0] = Al[r0];     al[m][1] = Al[r0 + 8*APAD];
                al[m][2] = Al[r0 + 4]; al[m][3] = Al[r0 + 8*APAD + 4];
            }
#pragma unroll
            for (int n = 0; n < 4; ++n){
                int kk = (32*wk + 8*n + g)*APAD + d0 + tg;
                bh[n][0] = Kh[kk]; bh[n][1] = Kh[kk + 4];
                bl[n][0] = Kl[kk]; bl[n][1] = Kl[kk + 4];
            }
#pragma unroll
            for (int n = 0; n < 4; ++n)
#pragma unroll
                for (int m = 0; m < 2; ++m){
                    mma_tf32(c[m][n], ah[m], bh[n]);
                    mma_tf32(c[m][n], ah[m], bl[n]);
                    mma_tf32(c[m][n], al[m], bh[n]);
                }
        }
        __syncthreads();   // all MMA reads of K done; xbuf rounds follow

        // pair-exchange: s = s(dh=0) + s(dh=1), then exp. 2 rounds x 4 pairs.
#pragma unroll
        for (int r = 0; r < 2; ++r){
            if (dh == 0 && (pos >> 2) == r){
                float* xb = xbuf + (pos & 3)*1024;
#pragma unroll
                for (int m = 0; m < 2; ++m)
#pragma unroll
                    for (int n = 0; n < 4; ++n)
#pragma unroll
                        for (int j = 0; j < 4; ++j)
                            xb[(m*16 + n*4 + j)*32 + lane] = c[m][n][j];
            }
            __syncthreads();
            if (dh == 1 && (pos >> 2) == r){
                const float* xb = xbuf + (pos & 3)*1024;
#pragma unroll
                for (int m = 0; m < 2; ++m)
#pragma unroll
                    for (int n = 0; n < 4; ++n){
                        float s0 = c[m][n][0] + xb[(m*16+n*4+0)*32 + lane];
                        float s1 = c[m][n][1] + xb[(m*16+n*4+1)*32 + lane];
                        float s2 = c[m][n][2] + xb[(m*16+n*4+2)*32 + lane];
                        float s3 = c[m][n][3] + xb[(m*16+n*4+3)*32 + lane];
                        z[2*m]   += __expf(s0) + __expf(s1);
                        z[2*m+1] += __expf(s2) + __expf(s3);
                    }
            }
            __syncthreads();   // xbuf free; after r=1 also gates next K stage
        }
    }

    // dh=1 warps hold z. Lanes tg=0..3 of a group hold disjoint key-cols.
    if (dh == 1){
#pragma unroll
        for (int j = 0; j < 4; ++j){
            z[j] += __shfl_xor_sync(0xffffffffu, z[j], 1);
            z[j] += __shfl_xor_sync(0xffffffffu, z[j], 2);
        }
        if (tg == 0){
#pragma unroll
            for (int m = 0; m < 2; ++m){
                zr[wk*128 + 32*wq + 16*m + g]     = z[2*m];
                zr[wk*128 + 32*wq + 16*m + 8 + g] = z[2*m+1];
            }
        }
    }
    __syncthreads();
    if (t < 128)
        g_zpart[kq][hb*SEQ + qt*128 + t] = zr[t] + zr[128 + t];
}

// ---------------------------------------------------------------------------
// Kernel 1: warp-per-row exact top-32 (value desc, index asc).
// Threshold prefilter + REDUX.UMAX selection; exact full-row fallback.
// ---------------------------------------------------------------------------
#define TH0 1.9f
#define CANDMAX 128

__global__ __launch_bounds__(256) void topk_kernel(const float* __restrict__ aw){
    __shared__ u64 cand[8][CANDMAX];
    __shared__ u32 cnt[8];
    const int wid = threadIdx.x >> 5, lane = threadIdx.x & 31;
    const int row = blockIdx.x*8 + wid;
    const float* __restrict__ ar = aw + (size_t)row * SEQ;
    if (lane == 0) cnt[wid] = 0;
    __syncwarp();
#pragma unroll
    for (int it = 0; it < 16; ++it){
        float4 v = ((const float4*)ar)[it*32 + lane];
        float vs[4] = {v.x, v.y, v.z, v.w};
#pragma unroll
        for (int j = 0; j < 4; ++j){
            if (vs[j] >= TH0){
                u32 pos = atomicAdd(&cnt[wid], 1u);
                int idx = (it*32 + lane)*4 + j;
                if (pos < CANDMAX)
                    cand[wid][pos] = ((u64)fkey(vs[j]) << 32) | (u32)(SEQ-1-idx);
            }
        }
    }
    __syncwarp();
    u32 nc = cnt[wid];
    int* outp = g_topk + (size_t)row * TOPK;

    if (nc >= TOPK && nc <= CANDMAX){
        u32 khi[4], klo[4];
#pragma unroll
        for (int j = 0; j < 4; ++j){
            u32 p = lane + j*32;
            u64 c = (p < nc) ? cand[wid][p] : 0ull;
            khi[j] = (u32)(c >> 32);
            klo[j] = (u32)c;
        }
        for (int r = 0; r < TOPK; ++r){
            u32 loc = max(max(khi[0], khi[1]), max(khi[2], khi[3]));
            u32 wmax = __reduce_max_sync(0xffffffffu, loc);
            u32 ci = 0;
#pragma unroll
            for (int j = 0; j < 4; ++j) if (khi[j] == wmax) ci = max(ci, klo[j]);
            u32 wi = __reduce_max_sync(0xffffffffu, ci);
            if (lane == 0) outp[r] = (SEQ-1) - (int)wi;
#pragma unroll
            for (int j = 0; j < 4; ++j)
                if (khi[j] == wmax && klo[j] == wi) khi[j] = 0u;
        }
    } else {
        u64 W = ~0ull;
        for (int r = 0; r < TOPK; ++r){
            u64 loc = 0;
            for (int j = 0; j < 64; ++j){
                int idx = lane + j*32;
                u64 key = ((u64)fkey(ar[idx]) << 32) | (u32)(SEQ-1-idx);
                if (key < W && key > loc) loc = key;
            }
#pragma unroll
            for (int o = 16; o; o >>= 1){
                u64 w = __shfl_xor_sync(0xffffffffu, loc, o);
                loc = w > loc ? w : loc;
            }
            if (lane == 0) outp[r] = (SEQ-1) - (int)(u32)loc;
            W = loc;
        }
    }
}

// ---------------------------------------------------------------------------
// Kernel 3: recompute 32 selected scores (full fp32), renormalize with
// w_i = e^{s_i} / (sumE + 1e-5*Z), V gather, fused LayerNorm.
// ---------------------------------------------------------------------------
__global__ __launch_bounds__(256) void out_kernel(
    const float* __restrict__ q, const float* __restrict__ k, const float* __restrict__ v,
    const float* __restrict__ gamma, const float* __restrict__ beta, float* __restrict__ out)
{
    const int bs = blockIdx.x;
    const int b = bs >> 11, s = bs & (SEQ-1);
    const int t = threadIdx.x, h = t >> 5, lane = t & 31;
    const int row = (b*NH + h)*SEQ + s;
    __shared__ float se[8][32];
    __shared__ int   sk[8][32];
    __shared__ float sout[1024];
    __shared__ float sred[8][2];

    const float* qp = q + (size_t)(b*SEQ + s)*DM + h*HD;
    float4 q4 = ((const float4*)qp)[lane];
    float Zrow = g_zpart[0][row] + g_zpart[1][row] + g_zpart[2][row] + g_zpart[3][row];
    sk[h][lane] = g_topk[(size_t)row*TOPK + lane];
    __syncwarp();
    const float* kb = k + (size_t)b*SEQ*DM + h*HD;
    const float* vb = v + (size_t)b*SEQ*DM + h*HD;

    float sumE = 0.f;
#pragma unroll 4
    for (int j = 0; j < 32; ++j){
        int kj = sk[h][j];
        float4 k4 = ((const float4*)(kb + (size_t)kj*DM))[lane];
        float p = q4.x*k4.x + q4.y*k4.y + q4.z*k4.z + q4.w*k4.w;
#pragma unroll
        for (int o = 16; o; o >>= 1) p += __shfl_xor_sync(0xffffffffu, p, o);
        float e = __expf(p);
        sumE += e;
        if (lane == 0) se[h][j] = e;
    }
    __syncwarp();
    float rden = 1.f / (sumE + 1e-5f*Zrow);

    float4 acc = make_float4(0.f,0.f,0.f,0.f);
#pragma unroll 4
    for (int j = 0; j < 32; ++j){
        float w = se[h][j] * rden;
        int kj = sk[h][j];
        float4 v4 = ((const float4*)(vb + (size_t)kj*DM))[lane];
        acc.x += w*v4.x; acc.y += w*v4.y; acc.z += w*v4.z; acc.w += w*v4.w;
    }
    ((float4*)sout)[h*32 + lane] = acc;
    __syncthreads();

    float4 x = ((const float4*)sout)[t];
    float ps = x.x + x.y + x.z + x.w;
    float pq = x.x*x.x + x.y*x.y + x.z*x.z + x.w*x.w;
#pragma unroll
    for (int o = 16; o; o >>= 1){
        ps += __shfl_xor_sync(0xffffffffu, ps, o);
        pq += __shfl_xor_sync(0xffffffffu, pq, o);
    }
    if (lane == 0){ sred[h][0] = ps; sred[h][1] = pq; }
    __syncthreads();
    float Sm = 0.f, Sq = 0.f;
#pragma unroll
    for (int w = 0; w < 8; ++w){ Sm += sred[w][0]; Sq += sred[w][1]; }
    float mu  = Sm * (1.f/1024.f);
    float var = Sq * (1.f/1024.f) - mu*mu;
    float r   = rsqrtf(var + 1e-5f);
    float4 g4 = ((const float4*)gamma)[t];
    float4 b4 = ((const float4*)beta)[t];
    float4 y;
    y.x = (x.x-mu)*r*g4.x + b4.x;
    y.y = (x.y-mu)*r*g4.y + b4.y;
    y.z = (x.z-mu)*r*g4.z + b4.z;
    y.w = (x.w-mu)*r*g4.w + b4.w;
    ((float4*)(out + (size_t)bs*DM))[t] = y;
}

// ---------------------------------------------------------------------------
extern "C" void kernel_launch(void* const* d_in, const int* in_sizes, int n_in,
                              void* d_out, int out_size){
    const float* q     = (const float*)d_in[0];
    const float* k     = (const float*)d_in[1];
    const float* v     = (const float*)d_in[2];
    const float* aw    = (const float*)d_in[3];
    const float* gamma = (const float*)d_in[4];
    const float* beta  = (const float*)d_in[5];
    float* out = (float*)d_out;

    cudaFuncSetAttribute(mz_kernel, cudaFuncAttributeMaxDynamicSharedMemorySize, SMEMZ_BYTES);

    // mz first: independent of topk, and lands under the ncu capture window.
    mz_kernel<<<16*16*4, 512, SMEMZ_BYTES>>>(q, k);
    topk_kernel<<<NROWS/8, 256>>>(aw);
    out_kernel<<<NB*SEQ, 256>>>(q, k, v, gamma, beta, out);
}

// round 16
// speedup vs baseline: 1.0417x; 1.0417x over previous
#include <cuda_runtime.h>

typedef unsigned long long u64;
typedef unsigned int u32;

#define SEQ   2048
#define DM    1024
#define NH    8
#define HD    128
#define NB    2
#define NROWS (NB*NH*SEQ)
#define TOPK  32

__device__ int   g_topk[NROWS*TOPK];
__device__ float g_zpart[4][NROWS];

__device__ __forceinline__ u32 fkey(float f){
    u32 b = __float_as_uint(f);
    return (b & 0x80000000u) ? ~b : (b | 0x80000000u);
}

// ===================== tf32 helpers =====================
__device__ __forceinline__ u32 cvt_tf32(float x){
    u32 r; asm("cvt.rna.tf32.f32 %0, %1;" : "=r"(r) : "f"(x)); return r;
}
__device__ __forceinline__ void mma_tf32(float* c, const u32* a, const u32* b){
    asm volatile("mma.sync.aligned.m16n8k8.row.col.f32.tf32.tf32.f32 "
        "{%0,%1,%2,%3}, {%4,%5,%6,%7}, {%8,%9}, {%0,%1,%2,%3};"
        : "+f"(c[0]), "+f"(c[1]), "+f"(c[2]), "+f"(c[3])
        : "r"(a[0]), "r"(a[1]), "r"(a[2]), "r"(a[3]), "r"(b[0]), "r"(b[1]));
}

// ---------------------------------------------------------------------------
// Kernel 2 (launched FIRST for ncu): partial Z per (hb, 128-q tile, 512-key
// slice), tf32 mma.sync 3-pass (hh + hl + lh). R13 block structure:
// 256 thr / 8 warps, warp (wq 0..3, wk 0..1) = 32q x 32k, 64-key subtiles.
// NEW: fragment-major smem layout. Element (row,dim) is stored at the exact
// (lane, j) slot its consuming fragment needs:
//   A (Q): [rb=row>>4][sl=dim>>3][lane=4*(row&7)+(dim&3)][j=2*((dim>>2)&1)+((row>>3)&1)]
//   B (K): [nb=key>>3][sl][lane=4*(key&7)+(dim&3)][j=(dim>>2)&1]
// so per slice: 4x LDS.128 (a hi+lo) + 8x LDS.64 (b hi+lo) = 12 wide loads
// instead of 32 scalar LDS.32. XOR swizzle ^((sl&7)<<2) keeps compute reads
// conflict-free and bounds staging STS conflicts to 2-way.
// No max-tracking (|score| <~ 75, exp can't overflow fp32).
// ---------------------------------------------------------------------------
#define QH_OFF 0
#define QL_OFF 16384
#define KH_OFF 32768
#define KL_OFF 40960
#define ZR_OFF 49152
#define SMEMZ_BYTES ((ZR_OFF + 256)*4)   /* 197632 B */

__global__ __launch_bounds__(256,1) void mz_kernel(const float* __restrict__ q,
                                                   const float* __restrict__ k){
    extern __shared__ u32 sm[];
    u32* QH = sm + QH_OFF;
    u32* QL = sm + QL_OFF;
    u32* KH = sm + KH_OFF;
    u32* KL = sm + KL_OFF;
    float* zr = (float*)(sm + ZR_OFF);

    const int t  = threadIdx.x;
    const int hb = blockIdx.x >> 6, qt = (blockIdx.x >> 2) & 15, kq = blockIdx.x & 3;
    const int b  = hb >> 3, h = hb & 7;
    const float* Qg = q + ((size_t)(b*SEQ + qt*128))*DM + h*HD;
    const float* Kg = k + ((size_t)(b*SEQ + kq*512))*DM + h*HD;

    const int lane = t & 31, wid = t >> 5;
    const int g = lane >> 2, tg = lane & 3;
    const int wq = wid >> 1, wk = wid & 1;

    // ---- Q tile -> fragment-major smem (tf32 hi/lo), once ----
#pragma unroll
    for (int mm = 0; mm < 16; ++mm){
        int chunk = mm*256 + t;
        int qr = chunk >> 5, c4 = (chunk & 31)*4;
        float4 v = *(const float4*)(Qg + (size_t)qr*DM + c4);
        float xs[4] = {v.x, v.y, v.z, v.w};
        int rb = qr >> 4, rowhi = (qr >> 3) & 1, lane4 = (qr & 7) << 2;
#pragma unroll
        for (int qd = 0; qd < 4; ++qd){
            int d = c4 + qd;
            int sl = d >> 3;
            int j = (((d >> 2) & 1) << 1) | rowhi;
            u32 idx = (u32)((rb*16 + sl)*128) +
                      ((((u32)(lane4 | (d & 3)) << 2) | (u32)j) ^ (((u32)sl & 7u) << 2));
            u32 hi = cvt_tf32(xs[qd]);
            QH[idx] = hi;
            QL[idx] = cvt_tf32(xs[qd] - __uint_as_float(hi));
        }
    }

    float z[4] = {0.f, 0.f, 0.f, 0.f};
    float4 pf[8];

    // prefetch K subtile 0 (64 keys x 128 dims)
#pragma unroll
    for (int i = 0; i < 8; ++i){
        int chunk = i*256 + t;
        int kk = chunk >> 5, c4 = (chunk & 31)*4;
        pf[i] = *(const float4*)(Kg + (size_t)kk*DM + c4);
    }

    for (int s = 0; s < 8; ++s){
        // stage prefetched subtile into fragment-major layout
#pragma unroll
        for (int i = 0; i < 8; ++i){
            int chunk = i*256 + t;
            int kk = chunk >> 5, c4 = (chunk & 31)*4;
            int nb = kk >> 3, lane4 = (kk & 7) << 2;
            float xs[4] = {pf[i].x, pf[i].y, pf[i].z, pf[i].w};
#pragma unroll
            for (int qd = 0; qd < 4; ++qd){
                int d = c4 + qd;
                int sl = d >> 3;
                int j = (d >> 2) & 1;
                u32 idx = (u32)((nb*16 + sl)*64) +
                          ((((u32)(lane4 | (d & 3)) << 1) | (u32)j) ^ (((u32)sl & 7u) << 2));
                u32 hi = cvt_tf32(xs[qd]);
                KH[idx] = hi;
                KL[idx] = cvt_tf32(xs[qd] - __uint_as_float(hi));
            }
        }
        __syncthreads();

        // prefetch next subtile during compute
        if (s < 7){
#pragma unroll
            for (int i = 0; i < 8; ++i){
                int chunk = i*256 + t;
                int kk = chunk >> 5, c4 = (chunk & 31)*4;
                pf[i] = *(const float4*)(Kg + (size_t)((s+1)*64 + kk)*DM + c4);
            }
        }

        float c[2][4][4];
#pragma unroll
        for (int m = 0; m < 2; ++m)
#pragma unroll
            for (int n = 0; n < 4; ++n)
#pragma unroll
                for (int j = 0; j < 4; ++j) c[m][n][j] = 0.f;

#pragma unroll 4
        for (int sl = 0; sl < 16; ++sl){
            u32 swz = ((u32)sl & 7u) << 2;
            uint4 ahv[2], alv[2];
            uint2 bhv[4], blv[4];
#pragma unroll
            for (int m = 0; m < 2; ++m){
                int rb = 2*wq + m;
                u32 base = (u32)((rb*16 + sl)*128) + (((u32)lane << 2) ^ swz);
                ahv[m] = *(const uint4*)&QH[base];
                alv[m] = *(const uint4*)&QL[base];
            }
#pragma unroll
            for (int n = 0; n < 4; ++n){
                int nb = 4*wk + n;
                u32 base = (u32)((nb*16 + sl)*64) + (((u32)lane << 1) ^ swz);
                bhv[n] = *(const uint2*)&KH[base];
                blv[n] = *(const uint2*)&KL[base];
            }
#pragma unroll
            for (int n = 0; n < 4; ++n)
#pragma unroll
                for (int m = 0; m < 2; ++m){
                    mma_tf32(c[m][n], &ahv[m].x, &bhv[n].x);
                    mma_tf32(c[m][n], &ahv[m].x, &blv[n].x);
                    mma_tf32(c[m][n], &alv[m].x, &bhv[n].x);
                }
        }

        // epilogue: z += exp(score); c[m][n]: rows (g, g+8), cols (2tg, 2tg+1)
#pragma unroll
        for (int m = 0; m < 2; ++m)
#pragma unroll
            for (int n = 0; n < 4; ++n){
                z[2*m]   += __expf(c[m][n][0]) + __expf(c[m][n][1]);
                z[2*m+1] += __expf(c[m][n][2]) + __expf(c[m][n][3]);
            }
        __syncthreads();   // K smem reused next subtile
    }

    // lanes tg=0..3 of each group hold disjoint key-columns: shfl-reduce
#pragma unroll
    for (int j = 0; j < 4; ++j){
        z[j] += __shfl_xor_sync(0xffffffffu, z[j], 1);
        z[j] += __shfl_xor_sync(0xffffffffu, z[j], 2);
    }
    if (tg == 0){
#pragma unroll
        for (int m = 0; m < 2; ++m){
            zr[wk*128 + 32*wq + 16*m + g]     = z[2*m];
            zr[wk*128 + 32*wq + 16*m + 8 + g] = z[2*m+1];
        }
    }
    __syncthreads();
    if (t < 128)
        g_zpart[kq][hb*SEQ + qt*128 + t] = zr[t] + zr[128 + t];
}

// ---------------------------------------------------------------------------
// Kernel 1: warp-per-row exact top-32 (value desc, index asc).
// Threshold prefilter + REDUX.UMAX selection; exact full-row fallback.
// ---------------------------------------------------------------------------
#define TH0 1.9f
#define CANDMAX 128

__global__ __launch_bounds__(256) void topk_kernel(const float* __restrict__ aw){
    __shared__ u64 cand[8][CANDMAX];
    __shared__ u32 cnt[8];
    const int wid = threadIdx.x >> 5, lane = threadIdx.x & 31;
    const int row = blockIdx.x*8 + wid;
    const float* __restrict__ ar = aw + (size_t)row * SEQ;
    if (lane == 0) cnt[wid] = 0;
    __syncwarp();
#pragma unroll
    for (int it = 0; it < 16; ++it){
        float4 v = ((const float4*)ar)[it*32 + lane];
        float vs[4] = {v.x, v.y, v.z, v.w};
#pragma unroll
        for (int j = 0; j < 4; ++j){
            if (vs[j] >= TH0){
                u32 pos = atomicAdd(&cnt[wid], 1u);
                int idx = (it*32 + lane)*4 + j;
                if (pos < CANDMAX)
                    cand[wid][pos] = ((u64)fkey(vs[j]) << 32) | (u32)(SEQ-1-idx);
            }
        }
    }
    __syncwarp();
    u32 nc = cnt[wid];
    int* outp = g_topk + (size_t)row * TOPK;

    if (nc >= TOPK && nc <= CANDMAX){
        u32 khi[4], klo[4];
#pragma unroll
        for (int j = 0; j < 4; ++j){
            u32 p = lane + j*32;
            u64 c = (p < nc) ? cand[wid][p] : 0ull;
            khi[j] = (u32)(c >> 32);
            klo[j] = (u32)c;
        }
        for (int r = 0; r < TOPK; ++r){
            u32 loc = max(max(khi[0], khi[1]), max(khi[2], khi[3]));
            u32 wmax = __reduce_max_sync(0xffffffffu, loc);
            u32 ci = 0;
#pragma unroll
            for (int j = 0; j < 4; ++j) if (khi[j] == wmax) ci = max(ci, klo[j]);
            u32 wi = __reduce_max_sync(0xffffffffu, ci);
            if (lane == 0) outp[r] = (SEQ-1) - (int)wi;
#pragma unroll
            for (int j = 0; j < 4; ++j)
                if (khi[j] == wmax && klo[j] == wi) khi[j] = 0u;
        }
    } else {
        u64 W = ~0ull;
        for (int r = 0; r < TOPK; ++r){
            u64 loc = 0;
            for (int j = 0; j < 64; ++j){
                int idx = lane + j*32;
                u64 key = ((u64)fkey(ar[idx]) << 32) | (u32)(SEQ-1-idx);
                if (key < W && key > loc) loc = key;
            }
#pragma unroll
            for (int o = 16; o; o >>= 1){
                u64 w = __shfl_xor_sync(0xffffffffu, loc, o);
                loc = w > loc ? w : loc;
            }
            if (lane == 0) outp[r] = (SEQ-1) - (int)(u32)loc;
            W = loc;
        }
    }
}

// ---------------------------------------------------------------------------
// Kernel 3: recompute 32 selected scores (full fp32), renormalize with
// w_i = e^{s_i} / (sumE + 1e-5*Z), V gather, fused LayerNorm.
// ---------------------------------------------------------------------------
__global__ __launch_bounds__(256) void out_kernel(
    const float* __restrict__ q, const float* __restrict__ k, const float* __restrict__ v,
    const float* __restrict__ gamma, const float* __restrict__ beta, float* __restrict__ out)
{
    const int bs = blockIdx.x;
    const int b = bs >> 11, s = bs & (SEQ-1);
    const int t = threadIdx.x, h = t >> 5, lane = t & 31;
    const int row = (b*NH + h)*SEQ + s;
    __shared__ float se[8][32];
    __shared__ int   sk[8][32];
    __shared__ float sout[1024];
    __shared__ float sred[8][2];

    const float* qp = q + (size_t)(b*SEQ + s)*DM + h*HD;
    float4 q4 = ((const float4*)qp)[lane];
    float Zrow = g_zpart[0][row] + g_zpart[1][row] + g_zpart[2][row] + g_zpart[3][row];
    sk[h][lane] = g_topk[(size_t)row*TOPK + lane];
    __syncwarp();
    const float* kb = k + (size_t)b*SEQ*DM + h*HD;
    const float* vb = v + (size_t)b*SEQ*DM + h*HD;

    float sumE = 0.f;
#pragma unroll 4
    for (int j = 0; j < 32; ++j){
        int kj = sk[h][j];
        float4 k4 = ((const float4*)(kb + (size_t)kj*DM))[lane];
        float p = q4.x*k4.x + q4.y*k4.y + q4.z*k4.z + q4.w*k4.w;
#pragma unroll
        for (int o = 16; o; o >>= 1) p += __shfl_xor_sync(0xffffffffu, p, o);
        float e = __expf(p);
        sumE += e;
        if (lane == 0) se[h][j] = e;
    }
    __syncwarp();
    float rden = 1.f / (sumE + 1e-5f*Zrow);

    float4 acc = make_float4(0.f,0.f,0.f,0.f);
#pragma unroll 4
    for (int j = 0; j < 32; ++j){
        float w = se[h][j] * rden;
        int kj = sk[h][j];
        float4 v4 = ((const float4*)(vb + (size_t)kj*DM))[lane];
        acc.x += w*v4.x; acc.y += w*v4.y; acc.z += w*v4.z; acc.w += w*v4.w;
    }
    ((float4*)sout)[h*32 + lane] = acc;
    __syncthreads();

    float4 x = ((const float4*)sout)[t];
    float ps = x.x + x.y + x.z + x.w;
    float pq = x.x*x.x + x.y*x.y + x.z*x.z + x.w*x.w;
#pragma unroll
    for (int o = 16; o; o >>= 1){
        ps += __shfl_xor_sync(0xffffffffu, ps, o);
        pq += __shfl_xor_sync(0xffffffffu, pq, o);
    }
    if (lane == 0){ sred[h][0] = ps; sred[h][1] = pq; }
    __syncthreads();
    float Sm = 0.f, Sq = 0.f;
#pragma unroll
    for (int w = 0; w < 8; ++w){ Sm += sred[w][0]; Sq += sred[w][1]; }
    float mu  = Sm * (1.f/1024.f);
    float var = Sq * (1.f/1024.f) - mu*mu;
    float r   = rsqrtf(var + 1e-5f);
    float4 g4 = ((const float4*)gamma)[t];
    float4 b4 = ((const float4*)beta)[t];
    float4 y;
    y.x = (x.x-mu)*r*g4.x + b4.x;
    y.y = (x.y-mu)*r*g4.y + b4.y;
    y.z = (x.z-mu)*r*g4.z + b4.z;
    y.w = (x.w-mu)*r*g4.w + b4.w;
    ((float4*)(out + (size_t)bs*DM))[t] = y;
}

// ---------------------------------------------------------------------------
extern "C" void kernel_launch(void* const* d_in, const int* in_sizes, int n_in,
                              void* d_out, int out_size){
    const float* q     = (const float*)d_in[0];
    const float* k     = (const float*)d_in[1];
    const float* v     = (const float*)d_in[2];
    const float* aw    = (const float*)d_in[3];
    const float* gamma = (const float*)d_in[4];
    const float* beta  = (const float*)d_in[5];
    float* out = (float*)d_out;

    cudaFuncSetAttribute(mz_kernel, cudaFuncAttributeMaxDynamicSharedMemorySize, SMEMZ_BYTES);

    // mz first: independent of topk, and lands under the ncu capture window.
    mz_kernel<<<16*16*4, 256, SMEMZ_BYTES>>>(q, k);
    topk_kernel<<<NROWS/8, 256>>>(aw);
    out_kernel<<<NB*SEQ, 256>>>(q, k, v, gamma, beta, out);
}